// round 2
// baseline (speedup 1.0000x reference)
#include <cuda_runtime.h>
#include <math.h>

#define TT 180
#define BB 512
#define II 108
#define HH 1024
#define VV 108
#define G4 4096
#define K1TOT 1136   // 1024 (h) + 112 (x padded 108->112)
#define NB 128
#define NTHR 256

// ---------------- static device scratch (no allocations) ----------------
__device__ float g_Wcat1[G4 * K1TOT];   // rows gate-interleaved: [W_hh1 | W_ih1 | pad]
__device__ float g_Wcat2[G4 * 2048];    // rows gate-interleaved: [W_ih2 | W_hh2]
__device__ float g_WfinT[HH * 128];     // W_fin^T padded V->128
__device__ float g_bias1[G4];           // packed (gate-interleaved) b_ih1+b_hh1
__device__ float g_bias2[G4];
__device__ float g_h1[2][BB * HH];      // double-buffered hidden states
__device__ float g_h2[2][BB * HH];
__device__ float g_c1[BB * HH];
__device__ float g_c2[BB * HH];
__device__ float g_m[BB * HH];          // mid linear output
__device__ unsigned g_arrive;
__device__ volatile unsigned g_release;

// packed row p -> original gate row n
__device__ __forceinline__ int prow_to_n(int p) {
    return (((p >> 5) & 3) << 10) + ((p >> 7) << 5) + (p & 31);
}

// ---------------- prep: pack weights, combine biases, zero state, reset barrier ----
__global__ void prep(const float* __restrict__ W_ih1, const float* __restrict__ W_hh1,
                     const float* __restrict__ b_ih1, const float* __restrict__ b_hh1,
                     const float* __restrict__ W_ih2, const float* __restrict__ W_hh2,
                     const float* __restrict__ b_ih2, const float* __restrict__ b_hh2,
                     const float* __restrict__ W_fin) {
    if (blockIdx.x == 0 && threadIdx.x == 0) { g_arrive = 0u; g_release = 0u; }
    const int n1 = G4 * K1TOT, n2 = G4 * 2048, nf = HH * 128, ns = BB * HH;
    const int total = n1 + n2 + nf + 2 * G4 + 6 * ns;
    for (int idx = blockIdx.x * blockDim.x + threadIdx.x; idx < total;
         idx += gridDim.x * blockDim.x) {
        int i = idx;
        if (i < n1) {
            int p = i / K1TOT, k = i - p * K1TOT;
            int n = prow_to_n(p);
            float v;
            if (k < HH) v = W_hh1[n * HH + k];
            else { int k2 = k - HH; v = (k2 < II) ? W_ih1[n * II + k2] : 0.f; }
            g_Wcat1[i] = v; continue;
        }
        i -= n1;
        if (i < n2) {
            int p = i >> 11, k = i & 2047;
            int n = prow_to_n(p);
            g_Wcat2[i] = (k < HH) ? W_ih2[n * HH + k] : W_hh2[n * HH + (k - HH)];
            continue;
        }
        i -= n2;
        if (i < nf) {
            int k = i >> 7, v = i & 127;
            g_WfinT[i] = (v < VV) ? W_fin[v * HH + k] : 0.f;
            continue;
        }
        i -= nf;
        if (i < G4) { int n = prow_to_n(i); g_bias1[i] = b_ih1[n] + b_hh1[n]; continue; }
        i -= G4;
        if (i < G4) { int n = prow_to_n(i); g_bias2[i] = b_ih2[n] + b_hh2[n]; continue; }
        i -= G4;
        if (i < ns) { g_h1[0][i] = 0.f; continue; } i -= ns;
        if (i < ns) { g_h1[1][i] = 0.f; continue; } i -= ns;
        if (i < ns) { g_h2[0][i] = 0.f; continue; } i -= ns;
        if (i < ns) { g_h2[1][i] = 0.f; continue; } i -= ns;
        if (i < ns) { g_c1[i]    = 0.f; continue; } i -= ns;
        g_c2[i] = 0.f;
    }
}

// ---------------- grid-wide barrier (128 co-resident blocks) ----------------
__device__ __forceinline__ void gsync(unsigned& expected) {
    __syncthreads();
    if (threadIdx.x == 0) {
        __threadfence();
        expected += NB;
        unsigned a = atomicAdd(&g_arrive, 1u) + 1u;
        if (a == expected) {
            g_release = expected;
        } else {
            while (g_release < expected) { __nanosleep(64); }
        }
        __threadfence();
    }
    __syncthreads();
}

__device__ __forceinline__ float sigmf(float x) { return 1.f / (1.f + expf(-x)); }

// dual-source A load (bypass L1: cross-SM mutable data)
__device__ __forceinline__ float4 ldA(const float* A1, const float* A2,
                                      int K1, int K2v, int row, int k) {
    if (A2 == nullptr || k < K1)
        return __ldcg(reinterpret_cast<const float4*>(A1 + (size_t)row * K1 + k));
    int c = k - K1;
    if (c < K2v)
        return __ldcg(reinterpret_cast<const float4*>(A2 + (size_t)row * K2v + c));
    return make_float4(0.f, 0.f, 0.f, 0.f);
}

// ------------- big GEMM (128x128 tile) with fused LSTM-cell epilogue -------------
// C_pre[m, p] = sum_k A[m,k] * W[p,k] + biasP[p]; then cell over 4 gates.
__device__ void gemm_big_cell(const float* A1, const float* A2, int K1, int K2v, int Ktot,
                              const float* __restrict__ W, const float* __restrict__ biasP,
                              float* hOut, float* cSt, int m0, int bn, float* sm) {
    float* As = sm;            // [2][8][128]
    float* Ws = sm + 2048;     // [2][8][128]
    const int tid = threadIdx.x;
    const int lr = tid >> 1;
    const int kof = (tid & 1) * 4;
    const int trow = tid >> 4, tcol = tid & 15;
    const int n0 = bn << 7;

    float acc[8][8];
#pragma unroll
    for (int i = 0; i < 8; i++)
#pragma unroll
        for (int j = 0; j < 8; j++) acc[i][j] = 0.f;

    float4 av = ldA(A1, A2, K1, K2v, m0 + lr, kof);
    float4 wv = __ldg(reinterpret_cast<const float4*>(W + (size_t)(n0 + lr) * Ktot + kof));
    int buf = 0;
    As[buf * 1024 + (kof + 0) * 128 + lr] = av.x;
    As[buf * 1024 + (kof + 1) * 128 + lr] = av.y;
    As[buf * 1024 + (kof + 2) * 128 + lr] = av.z;
    As[buf * 1024 + (kof + 3) * 128 + lr] = av.w;
    Ws[buf * 1024 + (kof + 0) * 128 + lr] = wv.x;
    Ws[buf * 1024 + (kof + 1) * 128 + lr] = wv.y;
    Ws[buf * 1024 + (kof + 2) * 128 + lr] = wv.z;
    Ws[buf * 1024 + (kof + 3) * 128 + lr] = wv.w;
    __syncthreads();

    for (int k0 = 8; k0 <= Ktot; k0 += 8) {
        const bool has_next = (k0 < Ktot);
        if (has_next) {
            av = ldA(A1, A2, K1, K2v, m0 + lr, k0 + kof);
            wv = __ldg(reinterpret_cast<const float4*>(W + (size_t)(n0 + lr) * Ktot + k0 + kof));
        }
        const float* Ab = As + buf * 1024;
        const float* Wb = Ws + buf * 1024;
#pragma unroll
        for (int kk = 0; kk < 8; kk++) {
            float a[8], b[8];
            float4 t;
            t = *reinterpret_cast<const float4*>(&Ab[kk * 128 + trow * 8]);
            a[0] = t.x; a[1] = t.y; a[2] = t.z; a[3] = t.w;
            t = *reinterpret_cast<const float4*>(&Ab[kk * 128 + trow * 8 + 4]);
            a[4] = t.x; a[5] = t.y; a[6] = t.z; a[7] = t.w;
            t = *reinterpret_cast<const float4*>(&Wb[kk * 128 + tcol * 8]);
            b[0] = t.x; b[1] = t.y; b[2] = t.z; b[3] = t.w;
            t = *reinterpret_cast<const float4*>(&Wb[kk * 128 + tcol * 8 + 4]);
            b[4] = t.x; b[5] = t.y; b[6] = t.z; b[7] = t.w;
#pragma unroll
            for (int i = 0; i < 8; i++)
#pragma unroll
                for (int j = 0; j < 8; j++) acc[i][j] += a[i] * b[j];
        }
        if (has_next) {
            buf ^= 1;
            As[buf * 1024 + (kof + 0) * 128 + lr] = av.x;
            As[buf * 1024 + (kof + 1) * 128 + lr] = av.y;
            As[buf * 1024 + (kof + 2) * 128 + lr] = av.z;
            As[buf * 1024 + (kof + 3) * 128 + lr] = av.w;
            Ws[buf * 1024 + (kof + 0) * 128 + lr] = wv.x;
            Ws[buf * 1024 + (kof + 1) * 128 + lr] = wv.y;
            Ws[buf * 1024 + (kof + 2) * 128 + lr] = wv.z;
            Ws[buf * 1024 + (kof + 3) * 128 + lr] = wv.w;
            __syncthreads();
        }
    }

    // epilogue: exchange gates via smem [128 packed-cols][129] then apply cell
    __syncthreads();
    float* epi = sm;
#pragma unroll
    for (int j = 0; j < 8; j++) {
        const int cp = tcol * 8 + j;
        const float bb = biasP[n0 + cp];
#pragma unroll
        for (int i = 0; i < 8; i++)
            epi[cp * 129 + trow * 8 + i] = acc[i][j] + bb;
    }
    __syncthreads();
    for (int e = tid; e < 128 * 32; e += NTHR) {
        const int jin = e & 31, ml = e >> 5;
        const float ig = sigmf(epi[(jin)      * 129 + ml]);
        const float fg = sigmf(epi[(32 + jin) * 129 + ml]);
        const float gg = tanhf(epi[(64 + jin) * 129 + ml]);
        const float og = sigmf(epi[(96 + jin) * 129 + ml]);
        const size_t idx = (size_t)(m0 + ml) * HH + (bn << 5) + jin;
        const float c = __ldcg(&cSt[idx]);
        const float cn = fg * c + ig * gg;
        cSt[idx] = cn;
        hOut[idx] = og * tanhf(cn);
    }
}

// ------------- mid GEMM: 64x64 tile, K=1024, C = A @ W^T + b -------------
__device__ void gemm_mid(const float* A, const float* __restrict__ W,
                         const float* __restrict__ bias, float* C,
                         int m0, int n0, float* sm) {
    float* As = sm;           // [2][8][64]
    float* Ws = sm + 1024;    // [2][8][64]
    const int tid = threadIdx.x;
    const int trow = tid >> 4, tcol = tid & 15;
    const bool isA = tid < 128;
    const int ll = isA ? tid : tid - 128;
    const int lr = ll >> 1, kof = (ll & 1) * 4;

    float acc[4][4];
#pragma unroll
    for (int i = 0; i < 4; i++)
#pragma unroll
        for (int j = 0; j < 4; j++) acc[i][j] = 0.f;

    float4 v;
    if (isA) v = __ldcg(reinterpret_cast<const float4*>(A + (size_t)(m0 + lr) * HH + kof));
    else     v = __ldg(reinterpret_cast<const float4*>(W + (size_t)(n0 + lr) * HH + kof));
    int buf = 0;
    {
        float* dst = (isA ? As : Ws) + buf * 512;
        dst[(kof + 0) * 64 + lr] = v.x; dst[(kof + 1) * 64 + lr] = v.y;
        dst[(kof + 2) * 64 + lr] = v.z; dst[(kof + 3) * 64 + lr] = v.w;
    }
    __syncthreads();

    for (int k0 = 8; k0 <= HH; k0 += 8) {
        const bool has_next = (k0 < HH);
        if (has_next) {
            if (isA) v = __ldcg(reinterpret_cast<const float4*>(A + (size_t)(m0 + lr) * HH + k0 + kof));
            else     v = __ldg(reinterpret_cast<const float4*>(W + (size_t)(n0 + lr) * HH + k0 + kof));
        }
        const float* Ab = As + buf * 512;
        const float* Wb = Ws + buf * 512;
#pragma unroll
        for (int kk = 0; kk < 8; kk++) {
            float4 ta = *reinterpret_cast<const float4*>(&Ab[kk * 64 + trow * 4]);
            float4 tb = *reinterpret_cast<const float4*>(&Wb[kk * 64 + tcol * 4]);
            float a[4] = {ta.x, ta.y, ta.z, ta.w};
            float b[4] = {tb.x, tb.y, tb.z, tb.w};
#pragma unroll
            for (int i = 0; i < 4; i++)
#pragma unroll
                for (int j = 0; j < 4; j++) acc[i][j] += a[i] * b[j];
        }
        if (has_next) {
            buf ^= 1;
            float* dst = (isA ? As : Ws) + buf * 512;
            dst[(kof + 0) * 64 + lr] = v.x; dst[(kof + 1) * 64 + lr] = v.y;
            dst[(kof + 2) * 64 + lr] = v.z; dst[(kof + 3) * 64 + lr] = v.w;
            __syncthreads();
        }
    }
#pragma unroll
    for (int i = 0; i < 4; i++) {
        const int m = m0 + trow * 4 + i;
        const int n = n0 + tcol * 4;
        float4 o;
        o.x = acc[i][0] + bias[n + 0];
        o.y = acc[i][1] + bias[n + 1];
        o.z = acc[i][2] + bias[n + 2];
        o.w = acc[i][3] + bias[n + 3];
        *reinterpret_cast<float4*>(C + (size_t)m * HH + n) = o;
    }
}

// ------------- final linear + log_softmax (64 blocks active) -------------
__device__ void fin_phase(const float* c2, const float* __restrict__ bfin,
                          float* outT, int bid, float* sm) {
    if (bid >= 64) return;
    float* cs  = sm;                  // [8][1024]
    float* sh  = sm + 8192;           // [8][128]
    float* red = sm + 8192 + 1024;    // [16]
    const int b0 = bid * 8;
    const int tid = threadIdx.x;
    for (int idx = tid; idx < 8 * HH; idx += NTHR)
        cs[idx] = __ldcg(&c2[(size_t)(b0 + (idx >> 10)) * HH + (idx & 1023)]);
    __syncthreads();

    const int v = tid & 127;
    const int rh = (tid >> 7) * 4;
    float acc[4] = {0.f, 0.f, 0.f, 0.f};
    for (int k = 0; k < HH; k += 4) {
        const float w0 = g_WfinT[(k + 0) * 128 + v];
        const float w1 = g_WfinT[(k + 1) * 128 + v];
        const float w2 = g_WfinT[(k + 2) * 128 + v];
        const float w3 = g_WfinT[(k + 3) * 128 + v];
#pragma unroll
        for (int r = 0; r < 4; r++) {
            float4 cc = *reinterpret_cast<const float4*>(&cs[(rh + r) * 1024 + k]);
            acc[r] += cc.x * w0 + cc.y * w1 + cc.z * w2 + cc.w * w3;
        }
    }
    const float bb = (v < VV) ? bfin[v] : 0.f;
    float vals[4];
#pragma unroll
    for (int r = 0; r < 4; r++) {
        vals[r] = (v < VV) ? (acc[r] + bb) : -INFINITY;
        sh[(rh + r) * 128 + v] = vals[r];
    }
    __syncthreads();
    if (tid < 8) {
        const int r = tid;
        float mx = -INFINITY;
        for (int j = 0; j < VV; j++) mx = fmaxf(mx, sh[r * 128 + j]);
        float s = 0.f;
        for (int j = 0; j < VV; j++) s += expf(sh[r * 128 + j] - mx);
        red[r] = mx;
        red[8 + r] = logf(s);
    }
    __syncthreads();
    if (v < VV) {
#pragma unroll
        for (int r = 0; r < 4; r++)
            outT[(size_t)(b0 + rh + r) * VV + v] = vals[r] - red[rh + r] - red[8 + rh + r];
    }
}

// ---------------- persistent kernel: whole T loop, 4 grid syncs/step ----------------
__global__ void __launch_bounds__(NTHR)
lstm_persist(const float* __restrict__ x, const float* __restrict__ W_mid,
             const float* __restrict__ b_mid, const float* __restrict__ b_fin,
             float* __restrict__ out) {
    extern __shared__ float sm[];
    const int bid = blockIdx.x;
    unsigned expected = 0;
    const int m0b = (bid >> 5) << 7;   // big-gemm m tile
    const int bn  = bid & 31;          // big-gemm packed-n tile
    const int mtm = (bid >> 4) << 6;   // mid-gemm m tile
    const int ntm = (bid & 15) << 6;   // mid-gemm n tile

    for (int t = 0; t < TT; t++) {
        const int cur = t & 1, nxt = cur ^ 1;
        // layer 1: gates = h1 @ W_hh1^T + x_t @ W_ih1^T + b ; fused cell -> h1', c1
        gemm_big_cell(g_h1[cur], x + (size_t)t * BB * II, HH, II, K1TOT,
                      g_Wcat1, g_bias1, g_h1[nxt], g_c1, m0b, bn, sm);
        gsync(expected);
        // mid: m = c1 @ W_mid^T + b_mid
        gemm_mid(g_c1, W_mid, b_mid, g_m, mtm, ntm, sm);
        gsync(expected);
        // layer 2: gates = m @ W_ih2^T + h2 @ W_hh2^T + b ; fused cell -> h2', c2
        gemm_big_cell(g_m, g_h2[cur], HH, HH, 2048,
                      g_Wcat2, g_bias2, g_h2[nxt], g_c2, m0b, bn, sm);
        gsync(expected);
        // final: log_softmax(c2 @ W_fin^T + b_fin)
        fin_phase(g_c2, b_fin, out + (size_t)t * BB * VV, bid, sm);
        gsync(expected);
    }
}

// ---------------- launch ----------------
extern "C" void kernel_launch(void* const* d_in, const int* in_sizes, int n_in,
                              void* d_out, int out_size) {
    const float* x     = (const float*)d_in[0];
    const float* W_ih1 = (const float*)d_in[1];
    const float* W_hh1 = (const float*)d_in[2];
    const float* b_ih1 = (const float*)d_in[3];
    const float* b_hh1 = (const float*)d_in[4];
    const float* W_mid = (const float*)d_in[5];
    const float* b_mid = (const float*)d_in[6];
    const float* W_ih2 = (const float*)d_in[7];
    const float* W_hh2 = (const float*)d_in[8];
    const float* b_ih2 = (const float*)d_in[9];
    const float* b_hh2 = (const float*)d_in[10];
    const float* W_fin = (const float*)d_in[11];
    const float* b_fin = (const float*)d_in[12];
    float* out = (float*)d_out;

    static bool attr_done = false;
    if (!attr_done) {
        cudaFuncSetAttribute(lstm_persist,
                             cudaFuncAttributeMaxDynamicSharedMemorySize, 66048);
        attr_done = true;
    }

    prep<<<4096, 256>>>(W_ih1, W_hh1, b_ih1, b_hh1,
                        W_ih2, W_hh2, b_ih2, b_hh2, W_fin);
    lstm_persist<<<NB, NTHR, 66048>>>(x, W_mid, b_mid, b_fin, out);
}

// round 3
// speedup vs baseline: 1.0095x; 1.0095x over previous
#include <cuda_runtime.h>
#include <math.h>

#define TT 180
#define BB 512
#define II 108
#define HH 1024
#define VV 108
#define G4 4096
#define K1TOT 1136   // 1024 (h) + 112 (x padded 108->112)
#define NB 128
#define NTHR 256

// ---------------- static device scratch (no allocations) ----------------
__device__ float g_Wcat1[G4 * K1TOT];   // rows gate-interleaved: [W_hh1 | W_ih1 | pad]
__device__ float g_Wcat2[G4 * 2048];    // rows gate-interleaved: [W_ih2 | W_hh2]
__device__ float g_WfinT[HH * 128];     // W_fin^T padded V->128
__device__ float g_bias1[G4];           // packed (gate-interleaved) b_ih1+b_hh1
__device__ float g_bias2[G4];
__device__ float g_h1[2][BB * HH];      // double-buffered hidden states
__device__ float g_h2[2][BB * HH];
__device__ float g_c1[BB * HH];
__device__ float g_c2[BB * HH];
__device__ float g_m[BB * HH];          // mid linear output
__device__ unsigned g_arrive;
__device__ volatile unsigned g_release;

// packed row p -> original gate row n
__device__ __forceinline__ int prow_to_n(int p) {
    return (((p >> 5) & 3) << 10) + ((p >> 7) << 5) + (p & 31);
}

// ---------------- prep: pack weights, combine biases, zero state, reset barrier ----
__global__ void prep(const float* __restrict__ W_ih1, const float* __restrict__ W_hh1,
                     const float* __restrict__ b_ih1, const float* __restrict__ b_hh1,
                     const float* __restrict__ W_ih2, const float* __restrict__ W_hh2,
                     const float* __restrict__ b_ih2, const float* __restrict__ b_hh2,
                     const float* __restrict__ W_fin) {
    if (blockIdx.x == 0 && threadIdx.x == 0) { g_arrive = 0u; g_release = 0u; }
    const int n1 = G4 * K1TOT, n2 = G4 * 2048, nf = HH * 128, ns = BB * HH;
    const int total = n1 + n2 + nf + 2 * G4 + 6 * ns;
    for (int idx = blockIdx.x * blockDim.x + threadIdx.x; idx < total;
         idx += gridDim.x * blockDim.x) {
        int i = idx;
        if (i < n1) {
            int p = i / K1TOT, k = i - p * K1TOT;
            int n = prow_to_n(p);
            float v;
            if (k < HH) v = W_hh1[n * HH + k];
            else { int k2 = k - HH; v = (k2 < II) ? W_ih1[n * II + k2] : 0.f; }
            g_Wcat1[i] = v; continue;
        }
        i -= n1;
        if (i < n2) {
            int p = i >> 11, k = i & 2047;
            int n = prow_to_n(p);
            g_Wcat2[i] = (k < HH) ? W_ih2[n * HH + k] : W_hh2[n * HH + (k - HH)];
            continue;
        }
        i -= n2;
        if (i < nf) {
            int k = i >> 7, v = i & 127;
            g_WfinT[i] = (v < VV) ? W_fin[v * HH + k] : 0.f;
            continue;
        }
        i -= nf;
        if (i < G4) { int n = prow_to_n(i); g_bias1[i] = b_ih1[n] + b_hh1[n]; continue; }
        i -= G4;
        if (i < G4) { int n = prow_to_n(i); g_bias2[i] = b_ih2[n] + b_hh2[n]; continue; }
        i -= G4;
        if (i < ns) { g_h1[0][i] = 0.f; continue; } i -= ns;
        if (i < ns) { g_h1[1][i] = 0.f; continue; } i -= ns;
        if (i < ns) { g_h2[0][i] = 0.f; continue; } i -= ns;
        if (i < ns) { g_h2[1][i] = 0.f; continue; } i -= ns;
        if (i < ns) { g_c1[i]    = 0.f; continue; } i -= ns;
        g_c2[i] = 0.f;
    }
}

// ---------------- grid-wide barrier (128 co-resident blocks) ----------------
__device__ __forceinline__ void gsync(unsigned& expected) {
    __syncthreads();
    if (threadIdx.x == 0) {
        __threadfence();
        expected += NB;
        unsigned a = atomicAdd(&g_arrive, 1u) + 1u;
        if (a == expected) {
            g_release = expected;
        } else {
            while (g_release < expected) { __nanosleep(64); }
        }
        __threadfence();
    }
    __syncthreads();
}

__device__ __forceinline__ float sigmf(float x) { return 1.f / (1.f + expf(-x)); }

// dual-source A load (bypass L1: cross-SM mutable data)
__device__ __forceinline__ float4 ldA(const float* A1, const float* A2,
                                      int K1, int K2v, int row, int k) {
    if (A2 == nullptr || k < K1)
        return __ldcg(reinterpret_cast<const float4*>(A1 + (size_t)row * K1 + k));
    int c = k - K1;
    if (c < K2v)
        return __ldcg(reinterpret_cast<const float4*>(A2 + (size_t)row * K2v + c));
    return make_float4(0.f, 0.f, 0.f, 0.f);
}

// ------------- big GEMM (128x128 tile) with fused LSTM-cell epilogue -------------
// C_pre[m, p] = sum_k A[m,k] * W[p,k] + biasP[p]; then cell over 4 gates.
__device__ void gemm_big_cell(const float* A1, const float* A2, int K1, int K2v, int Ktot,
                              const float* __restrict__ W, const float* __restrict__ biasP,
                              float* hOut, float* cSt, int m0, int bn, float* sm) {
    float* As = sm;            // [2][8][128]
    float* Ws = sm + 2048;     // [2][8][128]
    const int tid = threadIdx.x;
    const int lr = tid >> 1;
    const int kof = (tid & 1) * 4;
    const int trow = tid >> 4, tcol = tid & 15;
    const int n0 = bn << 7;

    float acc[8][8];
#pragma unroll
    for (int i = 0; i < 8; i++)
#pragma unroll
        for (int j = 0; j < 8; j++) acc[i][j] = 0.f;

    float4 av = ldA(A1, A2, K1, K2v, m0 + lr, kof);
    float4 wv = __ldg(reinterpret_cast<const float4*>(W + (size_t)(n0 + lr) * Ktot + kof));
    int buf = 0;
    As[buf * 1024 + (kof + 0) * 128 + lr] = av.x;
    As[buf * 1024 + (kof + 1) * 128 + lr] = av.y;
    As[buf * 1024 + (kof + 2) * 128 + lr] = av.z;
    As[buf * 1024 + (kof + 3) * 128 + lr] = av.w;
    Ws[buf * 1024 + (kof + 0) * 128 + lr] = wv.x;
    Ws[buf * 1024 + (kof + 1) * 128 + lr] = wv.y;
    Ws[buf * 1024 + (kof + 2) * 128 + lr] = wv.z;
    Ws[buf * 1024 + (kof + 3) * 128 + lr] = wv.w;
    __syncthreads();

    for (int k0 = 8; k0 <= Ktot; k0 += 8) {
        const bool has_next = (k0 < Ktot);
        if (has_next) {
            av = ldA(A1, A2, K1, K2v, m0 + lr, k0 + kof);
            wv = __ldg(reinterpret_cast<const float4*>(W + (size_t)(n0 + lr) * Ktot + k0 + kof));
        }
        const float* Ab = As + buf * 1024;
        const float* Wb = Ws + buf * 1024;
#pragma unroll
        for (int kk = 0; kk < 8; kk++) {
            float a[8], b[8];
            float4 t;
            t = *reinterpret_cast<const float4*>(&Ab[kk * 128 + trow * 8]);
            a[0] = t.x; a[1] = t.y; a[2] = t.z; a[3] = t.w;
            t = *reinterpret_cast<const float4*>(&Ab[kk * 128 + trow * 8 + 4]);
            a[4] = t.x; a[5] = t.y; a[6] = t.z; a[7] = t.w;
            t = *reinterpret_cast<const float4*>(&Wb[kk * 128 + tcol * 8]);
            b[0] = t.x; b[1] = t.y; b[2] = t.z; b[3] = t.w;
            t = *reinterpret_cast<const float4*>(&Wb[kk * 128 + tcol * 8 + 4]);
            b[4] = t.x; b[5] = t.y; b[6] = t.z; b[7] = t.w;
#pragma unroll
            for (int i = 0; i < 8; i++)
#pragma unroll
                for (int j = 0; j < 8; j++) acc[i][j] += a[i] * b[j];
        }
        if (has_next) {
            buf ^= 1;
            As[buf * 1024 + (kof + 0) * 128 + lr] = av.x;
            As[buf * 1024 + (kof + 1) * 128 + lr] = av.y;
            As[buf * 1024 + (kof + 2) * 128 + lr] = av.z;
            As[buf * 1024 + (kof + 3) * 128 + lr] = av.w;
            Ws[buf * 1024 + (kof + 0) * 128 + lr] = wv.x;
            Ws[buf * 1024 + (kof + 1) * 128 + lr] = wv.y;
            Ws[buf * 1024 + (kof + 2) * 128 + lr] = wv.z;
            Ws[buf * 1024 + (kof + 3) * 128 + lr] = wv.w;
            __syncthreads();
        }
    }

    // epilogue: exchange gates via smem [128 packed-cols][129] then apply cell
    __syncthreads();
    float* epi = sm;
#pragma unroll
    for (int j = 0; j < 8; j++) {
        const int cp = tcol * 8 + j;
        const float bb = biasP[n0 + cp];
#pragma unroll
        for (int i = 0; i < 8; i++)
            epi[cp * 129 + trow * 8 + i] = acc[i][j] + bb;
    }
    __syncthreads();
    for (int e = tid; e < 128 * 32; e += NTHR) {
        const int jin = e & 31, ml = e >> 5;
        const float ig = sigmf(epi[(jin)      * 129 + ml]);
        const float fg = sigmf(epi[(32 + jin) * 129 + ml]);
        const float gg = tanhf(epi[(64 + jin) * 129 + ml]);
        const float og = sigmf(epi[(96 + jin) * 129 + ml]);
        const size_t idx = (size_t)(m0 + ml) * HH + (bn << 5) + jin;
        const float c = __ldcg(&cSt[idx]);
        const float cn = fg * c + ig * gg;
        cSt[idx] = cn;
        hOut[idx] = og * tanhf(cn);
    }
}

// ------------- mid GEMM: 64x64 tile, K=1024, C = A @ W^T + b -------------
__device__ void gemm_mid(const float* A, const float* __restrict__ W,
                         const float* __restrict__ bias, float* C,
                         int m0, int n0, float* sm) {
    float* As = sm;           // [2][8][64]
    float* Ws = sm + 1024;    // [2][8][64]
    const int tid = threadIdx.x;
    const int trow = tid >> 4, tcol = tid & 15;
    const bool isA = tid < 128;
    const int ll = isA ? tid : tid - 128;
    const int lr = ll >> 1, kof = (ll & 1) * 4;

    float acc[4][4];
#pragma unroll
    for (int i = 0; i < 4; i++)
#pragma unroll
        for (int j = 0; j < 4; j++) acc[i][j] = 0.f;

    float4 v;
    if (isA) v = __ldcg(reinterpret_cast<const float4*>(A + (size_t)(m0 + lr) * HH + kof));
    else     v = __ldg(reinterpret_cast<const float4*>(W + (size_t)(n0 + lr) * HH + kof));
    int buf = 0;
    {
        float* dst = (isA ? As : Ws) + buf * 512;
        dst[(kof + 0) * 64 + lr] = v.x; dst[(kof + 1) * 64 + lr] = v.y;
        dst[(kof + 2) * 64 + lr] = v.z; dst[(kof + 3) * 64 + lr] = v.w;
    }
    __syncthreads();

    for (int k0 = 8; k0 <= HH; k0 += 8) {
        const bool has_next = (k0 < HH);
        if (has_next) {
            if (isA) v = __ldcg(reinterpret_cast<const float4*>(A + (size_t)(m0 + lr) * HH + k0 + kof));
            else     v = __ldg(reinterpret_cast<const float4*>(W + (size_t)(n0 + lr) * HH + k0 + kof));
        }
        const float* Ab = As + buf * 512;
        const float* Wb = Ws + buf * 512;
#pragma unroll
        for (int kk = 0; kk < 8; kk++) {
            float4 ta = *reinterpret_cast<const float4*>(&Ab[kk * 64 + trow * 4]);
            float4 tb = *reinterpret_cast<const float4*>(&Wb[kk * 64 + tcol * 4]);
            float a[4] = {ta.x, ta.y, ta.z, ta.w};
            float b[4] = {tb.x, tb.y, tb.z, tb.w};
#pragma unroll
            for (int i = 0; i < 4; i++)
#pragma unroll
                for (int j = 0; j < 4; j++) acc[i][j] += a[i] * b[j];
        }
        if (has_next) {
            buf ^= 1;
            float* dst = (isA ? As : Ws) + buf * 512;
            dst[(kof + 0) * 64 + lr] = v.x; dst[(kof + 1) * 64 + lr] = v.y;
            dst[(kof + 2) * 64 + lr] = v.z; dst[(kof + 3) * 64 + lr] = v.w;
            __syncthreads();
        }
    }
#pragma unroll
    for (int i = 0; i < 4; i++) {
        const int m = m0 + trow * 4 + i;
        const int n = n0 + tcol * 4;
        float4 o;
        o.x = acc[i][0] + bias[n + 0];
        o.y = acc[i][1] + bias[n + 1];
        o.z = acc[i][2] + bias[n + 2];
        o.w = acc[i][3] + bias[n + 3];
        *reinterpret_cast<float4*>(C + (size_t)m * HH + n) = o;
    }
}

// ------------- final linear + log_softmax (64 blocks active) -------------
__device__ void fin_phase(const float* c2, const float* __restrict__ bfin,
                          float* outT, int bid, float* sm) {
    if (bid >= 64) return;
    float* cs  = sm;                  // [8][1024]
    float* sh  = sm + 8192;           // [8][128]
    float* red = sm + 8192 + 1024;    // [16]
    const int b0 = bid * 8;
    const int tid = threadIdx.x;
    for (int idx = tid; idx < 8 * HH; idx += NTHR)
        cs[idx] = __ldcg(&c2[(size_t)(b0 + (idx >> 10)) * HH + (idx & 1023)]);
    __syncthreads();

    const int v = tid & 127;
    const int rh = (tid >> 7) * 4;
    float acc[4] = {0.f, 0.f, 0.f, 0.f};
    for (int k = 0; k < HH; k += 4) {
        const float w0 = g_WfinT[(k + 0) * 128 + v];
        const float w1 = g_WfinT[(k + 1) * 128 + v];
        const float w2 = g_WfinT[(k + 2) * 128 + v];
        const float w3 = g_WfinT[(k + 3) * 128 + v];
#pragma unroll
        for (int r = 0; r < 4; r++) {
            float4 cc = *reinterpret_cast<const float4*>(&cs[(rh + r) * 1024 + k]);
            acc[r] += cc.x * w0 + cc.y * w1 + cc.z * w2 + cc.w * w3;
        }
    }
    const float bb = (v < VV) ? bfin[v] : 0.f;
    float vals[4];
#pragma unroll
    for (int r = 0; r < 4; r++) {
        vals[r] = (v < VV) ? (acc[r] + bb) : -INFINITY;
        sh[(rh + r) * 128 + v] = vals[r];
    }
    __syncthreads();
    if (tid < 8) {
        const int r = tid;
        float mx = -INFINITY;
        for (int j = 0; j < VV; j++) mx = fmaxf(mx, sh[r * 128 + j]);
        float s = 0.f;
        for (int j = 0; j < VV; j++) s += expf(sh[r * 128 + j] - mx);
        red[r] = mx;
        red[8 + r] = logf(s);
    }
    __syncthreads();
    if (v < VV) {
#pragma unroll
        for (int r = 0; r < 4; r++)
            outT[(size_t)(b0 + rh + r) * VV + v] = vals[r] - red[rh + r] - red[8 + rh + r];
    }
}

// ---------------- persistent kernel: whole T loop, 4 grid syncs/step ----------------
__global__ void __launch_bounds__(NTHR)
lstm_persist(const float* __restrict__ x, const float* __restrict__ W_mid,
             const float* __restrict__ b_mid, const float* __restrict__ b_fin,
             float* __restrict__ out) {
    extern __shared__ float sm[];
    const int bid = blockIdx.x;
    unsigned expected = 0;
    const int m0b = (bid >> 5) << 7;   // big-gemm m tile
    const int bn  = bid & 31;          // big-gemm packed-n tile
    const int mtm = (bid >> 4) << 6;   // mid-gemm m tile
    const int ntm = (bid & 15) << 6;   // mid-gemm n tile

    for (int t = 0; t < TT; t++) {
        const int cur = t & 1, nxt = cur ^ 1;
        // layer 1: gates = h1 @ W_hh1^T + x_t @ W_ih1^T + b ; fused cell -> h1', c1
        gemm_big_cell(g_h1[cur], x + (size_t)t * BB * II, HH, II, K1TOT,
                      g_Wcat1, g_bias1, g_h1[nxt], g_c1, m0b, bn, sm);
        gsync(expected);
        // mid: m = c1 @ W_mid^T + b_mid
        gemm_mid(g_c1, W_mid, b_mid, g_m, mtm, ntm, sm);
        gsync(expected);
        // layer 2: gates = m @ W_ih2^T + h2 @ W_hh2^T + b ; fused cell -> h2', c2
        gemm_big_cell(g_m, g_h2[cur], HH, HH, 2048,
                      g_Wcat2, g_bias2, g_h2[nxt], g_c2, m0b, bn, sm);
        gsync(expected);
        // final: log_softmax(c2 @ W_fin^T + b_fin)
        fin_phase(g_c2, b_fin, out + (size_t)t * BB * VV, bid, sm);
        gsync(expected);
    }
}

// ---------------- launch ----------------
extern "C" void kernel_launch(void* const* d_in, const int* in_sizes, int n_in,
                              void* d_out, int out_size) {
    const float* x     = (const float*)d_in[0];
    const float* W_ih1 = (const float*)d_in[1];
    const float* W_hh1 = (const float*)d_in[2];
    const float* b_ih1 = (const float*)d_in[3];
    const float* b_hh1 = (const float*)d_in[4];
    const float* W_mid = (const float*)d_in[5];
    const float* b_mid = (const float*)d_in[6];
    const float* W_ih2 = (const float*)d_in[7];
    const float* W_hh2 = (const float*)d_in[8];
    const float* b_ih2 = (const float*)d_in[9];
    const float* b_hh2 = (const float*)d_in[10];
    const float* W_fin = (const float*)d_in[11];
    const float* b_fin = (const float*)d_in[12];
    float* out = (float*)d_out;

    static bool attr_done = false;
    if (!attr_done) {
        cudaFuncSetAttribute(lstm_persist,
                             cudaFuncAttributeMaxDynamicSharedMemorySize, 66048);
        attr_done = true;
    }

    prep<<<4096, 256>>>(W_ih1, W_hh1, b_ih1, b_hh1,
                        W_ih2, W_hh2, b_ih2, b_hh2, W_fin);
    lstm_persist<<<NB, NTHR, 66048>>>(x, W_mid, b_mid, b_fin, out);
}

// round 12
// speedup vs baseline: 1.5390x; 1.5246x over previous
#include <cuda_runtime.h>
#include <cuda_bf16.h>
#include <mma.h>
#include <math.h>

using namespace nvcuda;

constexpr int TT = 180;
constexpr int BB = 512;
constexpr int II = 108;
constexpr int HH = 1024;
constexpr int VV = 108;
constexpr int G4 = 4096;
constexpr int NB = 128;
constexpr int NTHR = 256;
constexpr int K1P = 1152;
constexpr int K2P = 2048;
constexpr int PA = 72;
constexpr int PO = 132;
constexpr int DSM = 73984;

typedef __nv_bfloat16 bf;

__device__ bf g_W1h[(long)G4*K1P], g_W1l[(long)G4*K1P];
__device__ bf g_W2h[(long)G4*K2P], g_W2l[(long)G4*K2P];
__device__ bf g_Wmh[(long)HH*HH], g_Wml[(long)HH*HH];
__device__ bf g_xh[(long)TT*BB*128], g_xl[(long)TT*BB*128];
__device__ bf g_h1h[2][BB*HH], g_h1l[2][BB*HH];
__device__ bf g_h2h[2][BB*HH], g_h2l[2][BB*HH];
__device__ bf g_c1h[BB*HH], g_c1l[BB*HH];
__device__ bf g_msh[BB*HH], g_msl[BB*HH];
__device__ float g_c1[BB*HH], g_c2[BB*HH];
__device__ float g_bias1[G4], g_bias2[G4];
__device__ float g_WfinT[HH*128];
__device__ unsigned g_arrive;
__device__ volatile unsigned g_release;

__device__ __forceinline__ void split_bf(float v, bf& hi, bf& lo) {
    hi = __float2bfloat16(v);
    lo = __float2bfloat16(v - __bfloat162float(hi));
}

__device__ __forceinline__ float sigmf(float x) {
    return 1.f / (1.f + expf(-x));
}

__device__ __forceinline__ int prow_n(int p) {
    return ((p >> 5) & 3)*HH + (p >> 7)*32 + (p & 31);
}

__global__ void prep(const float* __restrict__ x,
                     const float* __restrict__ Wi1,
                     const float* __restrict__ Wh1,
                     const float* __restrict__ bi1,
                     const float* __restrict__ bh1,
                     const float* __restrict__ Wm,
                     const float* __restrict__ Wi2,
                     const float* __restrict__ Wh2,
                     const float* __restrict__ bi2,
                     const float* __restrict__ bh2,
                     const float* __restrict__ Wf) {
    if (blockIdx.x == 0 && threadIdx.x == 0) {
        g_arrive = 0u;
        g_release = 0u;
    }
    const long NW1 = (long)G4*K1P;
    const long NW2 = (long)G4*K2P;
    const long NWM = (long)HH*HH;
    const long NX = (long)TT*BB*128;
    const long NH = (long)BB*HH;
    const long total = NW1 + NW2 + NWM + NX + 6*NH + 2*G4 + (long)HH*128;
    long idx = blockIdx.x*(long)blockDim.x + threadIdx.x;
    const long stride = (long)gridDim.x*blockDim.x;
    for (; idx < total; idx += stride) {
        long i = idx;
        if (i < NW1) {
            int p = (int)(i / K1P);
            int k = (int)(i - (long)p*K1P);
            int n = prow_n(p);
            float v = 0.f;
            if (k < HH) v = Wh1[(long)n*HH + k];
            else if (k - HH < II) v = Wi1[(long)n*II + (k - HH)];
            bf hi, lo;
            split_bf(v, hi, lo);
            g_W1h[i] = hi;
            g_W1l[i] = lo;
            continue;
        }
        i -= NW1;
        if (i < NW2) {
            int p = (int)(i >> 11);
            int k = (int)(i & 2047);
            int n = prow_n(p);
            float v;
            if (k < HH) v = Wi2[(long)n*HH + k];
            else v = Wh2[(long)n*HH + (k - HH)];
            bf hi, lo;
            split_bf(v, hi, lo);
            g_W2h[i] = hi;
            g_W2l[i] = lo;
            continue;
        }
        i -= NW2;
        if (i < NWM) {
            float v = Wm[i];
            bf hi, lo;
            split_bf(v, hi, lo);
            g_Wmh[i] = hi;
            g_Wml[i] = lo;
            continue;
        }
        i -= NWM;
        if (i < NX) {
            int t = (int)(i / (BB*128));
            int r = (int)(i - (long)t*BB*128);
            int b = r >> 7;
            int kx = r & 127;
            float v = 0.f;
            if (kx < II) v = x[((long)t*BB + b)*II + kx];
            bf hi, lo;
            split_bf(v, hi, lo);
            g_xh[i] = hi;
            g_xl[i] = lo;
            continue;
        }
        i -= NX;
        if (i < 4*NH) {
            long a = i / NH;
            long off = i - a*NH;
            bf z = __float2bfloat16(0.f);
            if (a == 0) g_h1h[0][off] = z;
            else if (a == 1) g_h1l[0][off] = z;
            else if (a == 2) g_h2h[0][off] = z;
            else g_h2l[0][off] = z;
            continue;
        }
        i -= 4*NH;
        if (i < NH) { g_c1[i] = 0.f; continue; }
        i -= NH;
        if (i < NH) { g_c2[i] = 0.f; continue; }
        i -= NH;
        if (i < G4) {
            int n = prow_n((int)i);
            g_bias1[i] = bi1[n] + bh1[n];
            continue;
        }
        i -= G4;
        if (i < G4) {
            int n = prow_n((int)i);
            g_bias2[i] = bi2[n] + bh2[n];
            continue;
        }
        i -= G4;
        int k = (int)(i >> 7);
        int v = (int)(i & 127);
        g_WfinT[i] = (v < VV) ? Wf[(long)v*HH + k] : 0.f;
    }
}

__device__ __forceinline__ void gsync(unsigned& expected) {
    __syncthreads();
    if (threadIdx.x == 0) {
        __threadfence();
        expected += NB;
        unsigned a = atomicAdd(&g_arrive, 1u) + 1u;
        if (a == expected) g_release = expected;
        else while (g_release < expected) { __nanosleep(64); }
        __threadfence();
    }
    __syncthreads();
}

__device__ void big_phase(const bf* a1h, const bf* a1l, int a1w, int a1c,
                          const bf* a2h, const bf* a2l, int a2w,
                          const bf* wHi, const bf* wLo, int kW, int nch,
                          const float* biasP, float* cst,
                          bf* hOh, bf* hOl, bf* cOh, bf* cOl,
                          int mt, int nt, char* smb) {
    bf* sAh = (bf*)smb;
    bf* sAl = sAh + 128*PA;
    bf* sWh = sAl + 128*PA;
    bf* sWl = sWh + 128*PA;
    float* sout = (float*)smb;
    const int tid = threadIdx.x;
    const int wid = tid >> 5;
    const int wr = wid & 3;
    const int wc = wid >> 2;
    const int m0 = mt*128;
    const int n0 = nt*128;

    wmma::fragment<wmma::accumulator, 16, 16, 16, float> acc[2][4];
    for (int i = 0; i < 2; i++)
        for (int j = 0; j < 4; j++)
            wmma::fill_fragment(acc[i][j], 0.f);

    for (int c = 0; c < nch; c++) {
        const bf* ah;
        const bf* al;
        int aw, col;
        if (c < a1c) {
            ah = a1h; al = a1l; aw = a1w; col = c*64;
        } else {
            ah = a2h; al = a2l; aw = a2w; col = (c - a1c)*64;
        }
        for (int i = tid; i < 1024; i += NTHR) {
            int r = i >> 3;
            int cg = (i & 7)*8;
            const uint4* sa = (const uint4*)(ah + (size_t)(m0 + r)*aw + col + cg);
            const uint4* sb = (const uint4*)(al + (size_t)(m0 + r)*aw + col + cg);
            *(uint4*)(sAh + r*PA + cg) = __ldcg(sa);
            *(uint4*)(sAl + r*PA + cg) = __ldcg(sb);
        }
        for (int i = tid; i < 1024; i += NTHR) {
            int r = i >> 3;
            int cg = (i & 7)*8;
            const uint4* sa = (const uint4*)(wHi + (size_t)(n0 + r)*kW + c*64 + cg);
            const uint4* sb = (const uint4*)(wLo + (size_t)(n0 + r)*kW + c*64 + cg);
            *(uint4*)(sWh + r*PA + cg) = __ldg(sa);
            *(uint4*)(sWl + r*PA + cg) = __ldg(sb);
        }
        __syncthreads();
        for (int ks = 0; ks < 4; ks++) {
            wmma::fragment<wmma::matrix_a, 16, 16, 16, bf, wmma::row_major> fah[2];
            wmma::fragment<wmma::matrix_a, 16, 16, 16, bf, wmma::row_major> fal[2];
            for (int i = 0; i < 2; i++) {
                const bf* pa = sAh + (wr*32 + i*16)*PA + ks*16;
                const bf* pb = sAl + (wr*32 + i*16)*PA + ks*16;
                wmma::load_matrix_sync(fah[i], pa, PA);
                wmma::load_matrix_sync(fal[i], pb, PA);
            }
            for (int j = 0; j < 4; j++) {
                wmma::fragment<wmma::matrix_b, 16, 16, 16, bf, wmma::col_major> fwh;
                wmma::fragment<wmma::matrix_b, 16, 16, 16, bf, wmma::col_major> fwl;
                const bf* ph = sWh + (wc*64 + j*16)*PA + ks*16;
                const bf* pl = sWl + (wc*64 + j*16)*PA + ks*16;
                wmma::load_matrix_sync(fwh, ph, PA);
                wmma::load_matrix_sync(fwl, pl, PA);
                for (int i = 0; i < 2; i++) {
                    wmma::mma_sync(acc[i][j], fah[i], fwh, acc[i][j]);
                    wmma::mma_sync(acc[i][j], fal[i], fwh, acc[i][j]);
                    wmma::mma_sync(acc[i][j], fah[i], fwl, acc[i][j]);
                }
            }
        }
        __syncthreads();
    }

    for (int i = 0; i < 2; i++)
        for (int j = 0; j < 4; j++) {
            float* po = sout + (wr*32 + i*16)*PO + wc*64 + j*16;
            wmma::store_matrix_sync(po, acc[i][j], PO, wmma::mem_row_major);
        }
    __syncthreads();

    for (int e = tid; e < 4096; e += NTHR) {
        int ml = e >> 5;
        int jin = e & 31;
        const float* base = sout + ml*PO + jin;
        float ig = sigmf(base[0] + biasP[n0 + jin]);
        float fg = sigmf(base[32] + biasP[n0 + 32 + jin]);
        float gg = tanhf(base[64] + biasP[n0 + 64 + jin]);
        float og = sigmf(base[96] + biasP[n0 + 96 + jin]);
        int j = nt*32 + jin;
        size_t ci = (size_t)(m0 + ml)*HH + j;
        float cn = fg*cst[ci] + ig*gg;
        cst[ci] = cn;
        float hn = og*tanhf(cn);
        bf ha, hb;
        split_bf(hn, ha, hb);
        hOh[ci] = ha;
        hOl[ci] = hb;
        if (cOh != 0) {
            bf ca, cb;
            split_bf(cn, ca, cb);
            cOh[ci] = ca;
            cOl[ci] = cb;
        }
    }
    __syncthreads();
}

__device__ void mid_phase(const float* bm, int bid, char* smb) {
    bf* sAh = (bf*)smb;
    bf* sAl = sAh + 64*PA;
    bf* sWh = sAl + 64*PA;
    bf* sWl = sWh + 64*PA;
    float* sout = (float*)smb;
    const int tid = threadIdx.x;
    const int wid = tid >> 5;
    const int wr = wid & 3;
    const int wc = wid >> 2;
    const int m0 = (bid >> 4)*64;
    const int n0 = (bid & 15)*64;

    wmma::fragment<wmma::accumulator, 16, 16, 16, float> acc[2];
    wmma::fill_fragment(acc[0], 0.f);
    wmma::fill_fragment(acc[1], 0.f);

    for (int c = 0; c < 16; c++) {
        for (int i = tid; i < 512; i += NTHR) {
            int r = i >> 3;
            int cg = (i & 7)*8;
            size_t ga = (size_t)(m0 + r)*HH + c*64 + cg;
            *(uint4*)(sAh + r*PA + cg) = __ldcg((const uint4*)(g_c1h + ga));
            *(uint4*)(sAl + r*PA + cg) = __ldcg((const uint4*)(g_c1l + ga));
        }
        for (int i = tid; i < 512; i += NTHR) {
            int r = i >> 3;
            int cg = (i & 7)*8;
            size_t ga = (size_t)(n0 + r)*HH + c*64 + cg;
            *(uint4*)(sWh + r*PA + cg) = __ldg((const uint4*)(g_Wmh + ga));
            *(uint4*)(sWl + r*PA + cg) = __ldg((const uint4*)(g_Wml + ga));
        }
        __syncthreads();
        for (int ks = 0; ks < 4; ks++) {
            wmma::fragment<wmma::matrix_a, 16, 16, 16, bf, wmma::row_major> fah;
            wmma::fragment<wmma::matrix_a, 16, 16, 16, bf, wmma::row_major> fal;
            wmma::load_matrix_sync(fah, sAh + (wr*16)*PA + ks*16, PA);
            wmma::load_matrix_sync(fal, sAl + (wr*16)*PA + ks*16, PA);
            for (int j = 0; j < 2; j++) {
                wmma::fragment<wmma::matrix_b, 16, 16, 16, bf, wmma::col_major> fwh;
                wmma::fragment<wmma::matrix_b, 16, 16, 16, bf, wmma::col_major> fwl;
                const bf* ph = sWh + (wc*32 + j*16)*PA + ks*16;
                const bf* pl = sWl + (wc*32 + j*16)*PA + ks*16;
                wmma::load_matrix_sync(fwh, ph, PA);
                wmma::load_matrix_sync(fwl, pl, PA);
                wmma::mma_sync(acc[j], fah, fwh, acc[j]);
                wmma::mma_sync(acc[j], fal, fwh, acc[j]);
                wmma::mma_sync(acc[j], fah, fwl, acc[j]);
            }
        }
        __syncthreads();
    }

    for (int j = 0; j < 2; j++) {
        float* po = sout + (wr*16)*68 + wc*32 + j*16;
        wmma::store_matrix_sync(po, acc[j], 68, wmma::mem_row_major);
    }
    __syncthreads();

    for (int e = tid; e < 4096; e += NTHR) {
        int ml = e >> 6;
        int nl = e & 63;
        float v = sout[ml*68 + nl] + bm[n0 + nl];
        bf ha, hb;
        split_bf(v, ha, hb);
        size_t di = (size_t)(m0 + ml)*HH + n0 + nl;
        g_msh[di] = ha;
        g_msl[di] = hb;
    }
    __syncthreads();
}

__device__ void fin_phase(const float* __restrict__ bfin, float* outT,
                          int bid, char* smb) {
    if (bid >= 64) return;
    float* cs = (float*)smb;
    float* sh = (float*)(smb + 32768);
    float* red = (float*)(smb + 36864);
    const int b0 = bid*8;
    const int tid = threadIdx.x;
    for (int idx = tid; idx < 8*HH; idx += NTHR) {
        int rr = idx >> 10;
        int kk = idx & 1023;
        cs[idx] = __ldcg(&g_c2[(size_t)(b0 + rr)*HH + kk]);
    }
    __syncthreads();
    const int v = tid & 127;
    const int rh = (tid >> 7)*4;
    float a0 = 0.f, a1 = 0.f, a2 = 0.f, a3 = 0.f;
    for (int k = 0; k < HH; k += 4) {
        float w0 = g_WfinT[(k + 0)*128 + v];
        float w1 = g_WfinT[(k + 1)*128 + v];
        float w2 = g_WfinT[(k + 2)*128 + v];
        float w3 = g_WfinT[(k + 3)*128 + v];
        float4 c0 = *(const float4*)(cs + (rh + 0)*1024 + k);
        float4 c1 = *(const float4*)(cs + (rh + 1)*1024 + k);
        float4 c2 = *(const float4*)(cs + (rh + 2)*1024 + k);
        float4 c3 = *(const float4*)(cs + (rh + 3)*1024 + k);
        a0 += c0.x*w0 + c0.y*w1 + c0.z*w2 + c0.w*w3;
        a1 += c1.x*w0 + c1.y*w1 + c1.z*w2 + c1.w*w3;
        a2 += c2.x*w0 + c2.y*w1 + c2.z*w2 + c2.w*w3;
        a3 += c3.x*w0 + c3.y*w1 + c3.z*w2 + c3.w*w3;
    }
    float bb = (v < VV) ? bfin[v] : 0.f;
    float vv0 = (v < VV) ? (a0 + bb) : -1e30f;
    float vv1 = (v < VV) ? (a1 + bb) : -1e30f;
    float vv2 = (v < VV) ? (a2 + bb) : -1e30f;
    float vv3 = (v < VV) ? (a3 + bb) : -1e30f;
    sh[(rh + 0)*128 + v] = vv0;
    sh[(rh + 1)*128 + v] = vv1;
    sh[(rh + 2)*128 + v] = vv2;
    sh[(rh + 3)*128 + v] = vv3;
    __syncthreads();
    if (tid < 8) {
        float mx = -1e30f;
        for (int j = 0; j < VV; j++) mx = fmaxf(mx, sh[tid*128 + j]);
        float s = 0.f;
        for (int j = 0; j < VV; j++) s += expf(sh[tid*128 + j] - mx);
        red[tid] = mx;
        red[8 + tid] = logf(s);
    }
    __syncthreads();
    if (v < VV) {
        outT[(size_t)(b0 + rh + 0)*VV + v] = vv0 - red[rh + 0] - red[8 + rh + 0];
        outT[(size_t)(b0 + rh + 1)*VV + v] = vv1 - red[rh + 1] - red[8 + rh + 1];
        outT[(size_t)(b0 + rh + 2)*VV + v] = vv2 - red[rh + 2] - red[8 + rh + 2];
        outT[(size_t)(b0 + rh + 3)*VV + v] = vv3 - red[rh + 3] - red[8 + rh + 3];
    }
}

__global__ void __launch_bounds__(NTHR)
lstm_tc(const float* __restrict__ bm, const float* __restrict__ bfin,
        float* __restrict__ out) {
    extern __shared__ char smb[];
    const int bid = blockIdx.x;
    unsigned expected = 0;
    const int mt = bid >> 5;
    const int nt = bid & 31;

    for (int t = 0; t < TT; t++) {
        const int cur = t & 1;
        const int nxt = cur ^ 1;
        big_phase(g_h1h[cur], g_h1l[cur], HH, 16,
                  g_xh + (long)t*BB*128, g_xl + (long)t*BB*128, 128,
                  g_W1h, g_W1l, K1P, 18,
                  g_bias1, g_c1, g_h1h[nxt], g_h1l[nxt],
                  g_c1h, g_c1l, mt, nt, smb);
        gsync(expected);
        mid_phase(bm, bid, smb);
        gsync(expected);
        big_phase(g_msh, g_msl, HH, 16,
                  g_h2h[cur], g_h2l[cur], HH,
                  g_W2h, g_W2l, K2P, 32,
                  g_bias2, g_c2, g_h2h[nxt], g_h2l[nxt],
                  (bf*)0, (bf*)0, mt, nt, smb);
        gsync(expected);
        fin_phase(bfin, out + (size_t)t*BB*VV, bid, smb);
    }
}

extern "C" void kernel_launch(void* const* d_in, const int* in_sizes,
                              int n_in, void* d_out, int out_size) {
    const float* x = (const float*)d_in[0];
    const float* Wi1 = (const float*)d_in[1];
    const float* Wh1 = (const float*)d_in[2];
    const float* bi1 = (const float*)d_in[3];
    const float* bh1 = (const float*)d_in[4];
    const float* Wm = (const float*)d_in[5];
    const float* bm = (const float*)d_in[6];
    const float* Wi2 = (const float*)d_in[7];
    const float* Wh2 = (const float*)d_in[8];
    const float* bi2 = (const float*)d_in[9];
    const float* bh2 = (const float*)d_in[10];
    const float* Wf = (const float*)d_in[11];
    const float* bfin = (const float*)d_in[12];
    float* out = (float*)d_out;

    cudaFuncSetAttribute(lstm_tc,
                         cudaFuncAttributeMaxDynamicSharedMemorySize, DSM);
    prep<<<4096, 256>>>(x, Wi1, Wh1, bi1, bh1, Wm,
                        Wi2, Wh2, bi2, bh2, Wf);
    lstm_tc<<<NB, NTHR, DSM>>>(bm, bfin, out);
}

// round 13
// speedup vs baseline: 2.7032x; 1.7565x over previous
#include <cuda_runtime.h>
#include <cuda_bf16.h>
#include <cuda_pipeline.h>
#include <mma.h>
#include <math.h>

using namespace nvcuda;

constexpr int TT = 180;
constexpr int BB = 512;
constexpr int II = 108;
constexpr int HH = 1024;
constexpr int VV = 108;
constexpr int G4 = 4096;
constexpr int NB = 128;
constexpr int NTHR = 256;
constexpr int K1P = 1152;
constexpr int K2P = 2048;
constexpr int PA = 72;
constexpr int PO = 132;
constexpr int BUF = 128*PA;
constexpr int DSM = 2*4*BUF*2;

typedef __nv_bfloat16 bf;

__device__ bf g_W1h[(long)G4*K1P], g_W1l[(long)G4*K1P];
__device__ bf g_W2h[(long)G4*K2P], g_W2l[(long)G4*K2P];
__device__ bf g_Wmh[(long)HH*HH], g_Wml[(long)HH*HH];
__device__ bf g_xh[(long)TT*BB*128], g_xl[(long)TT*BB*128];
__device__ bf g_h1h[2][BB*HH], g_h1l[2][BB*HH];
__device__ bf g_h2h[2][BB*HH], g_h2l[2][BB*HH];
__device__ bf g_c1h[BB*HH], g_c1l[BB*HH];
__device__ bf g_msh[BB*HH], g_msl[BB*HH];
__device__ float g_c1[BB*HH], g_c2[BB*HH];
__device__ float g_bias1[G4], g_bias2[G4];
__device__ float g_WfinT[HH*128];
__device__ unsigned g_arrive;
__device__ volatile unsigned g_release;

__device__ __forceinline__ void split_bf(float v, bf& hi, bf& lo) {
    hi = __float2bfloat16(v);
    lo = __float2bfloat16(v - __bfloat162float(hi));
}

__device__ __forceinline__ float sigmf(float x) {
    return 1.f / (1.f + expf(-x));
}

__device__ __forceinline__ int prow_n(int p) {
    return ((p >> 5) & 3)*HH + (p >> 7)*32 + (p & 31);
}

__global__ void prep(const float* __restrict__ x,
                     const float* __restrict__ Wi1,
                     const float* __restrict__ Wh1,
                     const float* __restrict__ bi1,
                     const float* __restrict__ bh1,
                     const float* __restrict__ Wm,
                     const float* __restrict__ Wi2,
                     const float* __restrict__ Wh2,
                     const float* __restrict__ bi2,
                     const float* __restrict__ bh2,
                     const float* __restrict__ Wf) {
    if (blockIdx.x == 0 && threadIdx.x == 0) {
        g_arrive = 0u;
        g_release = 0u;
    }
    const long NW1 = (long)G4*K1P;
    const long NW2 = (long)G4*K2P;
    const long NWM = (long)HH*HH;
    const long NX = (long)TT*BB*128;
    const long NH = (long)BB*HH;
    const long total = NW1 + NW2 + NWM + NX + 6*NH + 2*G4 + (long)HH*128;
    long idx = blockIdx.x*(long)blockDim.x + threadIdx.x;
    const long stride = (long)gridDim.x*blockDim.x;
    for (; idx < total; idx += stride) {
        long i = idx;
        if (i < NW1) {
            int p = (int)(i / K1P);
            int k = (int)(i - (long)p*K1P);
            int n = prow_n(p);
            float v = 0.f;
            if (k < HH) v = Wh1[(long)n*HH + k];
            else if (k - HH < II) v = Wi1[(long)n*II + (k - HH)];
            bf hi, lo;
            split_bf(v, hi, lo);
            g_W1h[i] = hi;
            g_W1l[i] = lo;
            continue;
        }
        i -= NW1;
        if (i < NW2) {
            int p = (int)(i >> 11);
            int k = (int)(i & 2047);
            int n = prow_n(p);
            float v;
            if (k < HH) v = Wi2[(long)n*HH + k];
            else v = Wh2[(long)n*HH + (k - HH)];
            bf hi, lo;
            split_bf(v, hi, lo);
            g_W2h[i] = hi;
            g_W2l[i] = lo;
            continue;
        }
        i -= NW2;
        if (i < NWM) {
            float v = Wm[i];
            bf hi, lo;
            split_bf(v, hi, lo);
            g_Wmh[i] = hi;
            g_Wml[i] = lo;
            continue;
        }
        i -= NWM;
        if (i < NX) {
            int t = (int)(i / (BB*128));
            int r = (int)(i - (long)t*BB*128);
            int b = r >> 7;
            int kx = r & 127;
            float v = 0.f;
            if (kx < II) v = x[((long)t*BB + b)*II + kx];
            bf hi, lo;
            split_bf(v, hi, lo);
            g_xh[i] = hi;
            g_xl[i] = lo;
            continue;
        }
        i -= NX;
        if (i < 4*NH) {
            long a = i / NH;
            long off = i - a*NH;
            bf z = __float2bfloat16(0.f);
            if (a == 0) g_h1h[0][off] = z;
            else if (a == 1) g_h1l[0][off] = z;
            else if (a == 2) g_h2h[0][off] = z;
            else g_h2l[0][off] = z;
            continue;
        }
        i -= 4*NH;
        if (i < NH) { g_c1[i] = 0.f; continue; }
        i -= NH;
        if (i < NH) { g_c2[i] = 0.f; continue; }
        i -= NH;
        if (i < G4) {
            int n = prow_n((int)i);
            g_bias1[i] = bi1[n] + bh1[n];
            continue;
        }
        i -= G4;
        if (i < G4) {
            int n = prow_n((int)i);
            g_bias2[i] = bi2[n] + bh2[n];
            continue;
        }
        i -= G4;
        int k = (int)(i >> 7);
        int v = (int)(i & 127);
        g_WfinT[i] = (v < VV) ? Wf[(long)v*HH + k] : 0.f;
    }
}

__device__ __forceinline__ void gsync(unsigned& expected) {
    __syncthreads();
    if (threadIdx.x == 0) {
        __threadfence();
        expected += NB;
        unsigned a = atomicAdd(&g_arrive, 1u) + 1u;
        if (a == expected) g_release = expected;
        else while (g_release < expected) { __nanosleep(64); }
        __threadfence();
    }
    __syncthreads();
}

__device__ void big_phase(const bf* a1h, const bf* a1l, int a1w, int a1c,
                          const bf* a2h, const bf* a2l, int a2w,
                          const bf* wHi, const bf* wLo, int kW, int nch,
                          const float* biasP, float* cst,
                          bf* hOh, bf* hOl, bf* cOh, bf* cOl,
                          int mt, int nt, char* smb) {
    bf* base = (bf*)smb;
    float* sout = (float*)smb;
    const int tid = threadIdx.x;
    const int wid = tid >> 5;
    const int wr = wid & 3;
    const int wc = wid >> 2;
    const int m0 = mt*128;
    const int n0 = nt*128;

    wmma::fragment<wmma::accumulator, 16, 16, 16, float> acc[2][4];
    for (int i = 0; i < 2; i++)
        for (int j = 0; j < 4; j++)
            wmma::fill_fragment(acc[i][j], 0.f);

    auto pre = [&](int c, int s) {
        const bf* ah;
        const bf* al;
        int aw, col;
        if (c < a1c) {
            ah = a1h; al = a1l; aw = a1w; col = c*64;
        } else {
            ah = a2h; al = a2l; aw = a2w; col = (c - a1c)*64;
        }
        bf* dAh = base + (s*4 + 0)*BUF;
        bf* dAl = base + (s*4 + 1)*BUF;
        bf* dWh = base + (s*4 + 2)*BUF;
        bf* dWl = base + (s*4 + 3)*BUF;
        for (int i = tid; i < 1024; i += NTHR) {
            int r = i >> 3;
            int cg = (i & 7)*8;
            int so = r*PA + cg;
            __pipeline_memcpy_async(dAh + so, ah + (size_t)(m0 + r)*aw + col + cg, 16);
            __pipeline_memcpy_async(dAl + so, al + (size_t)(m0 + r)*aw + col + cg, 16);
            __pipeline_memcpy_async(dWh + so, wHi + (size_t)(n0 + r)*kW + c*64 + cg, 16);
            __pipeline_memcpy_async(dWl + so, wLo + (size_t)(n0 + r)*kW + c*64 + cg, 16);
        }
    };

    pre(0, 0);
    __pipeline_commit();
    for (int c = 0; c < nch; c++) {
        if (c + 1 < nch) {
            pre(c + 1, (c + 1) & 1);
            __pipeline_commit();
            __pipeline_wait_prior(1);
        } else {
            __pipeline_wait_prior(0);
        }
        __syncthreads();
        const int s = c & 1;
        bf* cAh = base + (s*4 + 0)*BUF;
        bf* cAl = base + (s*4 + 1)*BUF;
        bf* cWh = base + (s*4 + 2)*BUF;
        bf* cWl = base + (s*4 + 3)*BUF;
        for (int ks = 0; ks < 4; ks++) {
            wmma::fragment<wmma::matrix_a, 16, 16, 16, bf, wmma::row_major> fah[2];
            wmma::fragment<wmma::matrix_a, 16, 16, 16, bf, wmma::row_major> fal[2];
            for (int i = 0; i < 2; i++) {
                const bf* pa = cAh + (wr*32 + i*16)*PA + ks*16;
                const bf* pb = cAl + (wr*32 + i*16)*PA + ks*16;
                wmma::load_matrix_sync(fah[i], pa, PA);
                wmma::load_matrix_sync(fal[i], pb, PA);
            }
            for (int j = 0; j < 4; j++) {
                wmma::fragment<wmma::matrix_b, 16, 16, 16, bf, wmma::col_major> fwh;
                wmma::fragment<wmma::matrix_b, 16, 16, 16, bf, wmma::col_major> fwl;
                const bf* ph = cWh + (wc*64 + j*16)*PA + ks*16;
                const bf* pl = cWl + (wc*64 + j*16)*PA + ks*16;
                wmma::load_matrix_sync(fwh, ph, PA);
                wmma::load_matrix_sync(fwl, pl, PA);
                for (int i = 0; i < 2; i++) {
                    wmma::mma_sync(acc[i][j], fah[i], fwh, acc[i][j]);
                    wmma::mma_sync(acc[i][j], fal[i], fwh, acc[i][j]);
                    wmma::mma_sync(acc[i][j], fah[i], fwl, acc[i][j]);
                }
            }
        }
        __syncthreads();
    }

    for (int i = 0; i < 2; i++)
        for (int j = 0; j < 4; j++) {
            float* po = sout + (wr*32 + i*16)*PO + wc*64 + j*16;
            wmma::store_matrix_sync(po, acc[i][j], PO, wmma::mem_row_major);
        }
    __syncthreads();

    for (int e = tid; e < 4096; e += NTHR) {
        int ml = e >> 5;
        int jin = e & 31;
        const float* bse = sout + ml*PO + jin;
        float ig = sigmf(bse[0] + biasP[n0 + jin]);
        float fg = sigmf(bse[32] + biasP[n0 + 32 + jin]);
        float gg = tanhf(bse[64] + biasP[n0 + 64 + jin]);
        float og = sigmf(bse[96] + biasP[n0 + 96 + jin]);
        int j = nt*32 + jin;
        size_t ci = (size_t)(m0 + ml)*HH + j;
        float cn = fg*cst[ci] + ig*gg;
        cst[ci] = cn;
        float hn = og*tanhf(cn);
        bf ha, hb;
        split_bf(hn, ha, hb);
        hOh[ci] = ha;
        hOl[ci] = hb;
        if (cOh != 0) {
            bf ca, cb;
            split_bf(cn, ca, cb);
            cOh[ci] = ca;
            cOl[ci] = cb;
        }
    }
    __syncthreads();
}

__device__ void mid_phase(const float* bm, int bid, char* smb) {
    bf* base = (bf*)smb;
    float* sout = (float*)smb;
    const int tid = threadIdx.x;
    const int wid = tid >> 5;
    const int wr = wid & 3;
    const int wc = wid >> 2;
    const int m0 = (bid >> 4)*64;
    const int n0 = (bid & 15)*64;
    const int MB = 64*PA;

    wmma::fragment<wmma::accumulator, 16, 16, 16, float> acc[2];
    wmma::fill_fragment(acc[0], 0.f);
    wmma::fill_fragment(acc[1], 0.f);

    auto pre = [&](int c, int s) {
        bf* dAh = base + (s*4 + 0)*MB;
        bf* dAl = base + (s*4 + 1)*MB;
        bf* dWh = base + (s*4 + 2)*MB;
        bf* dWl = base + (s*4 + 3)*MB;
        for (int i = tid; i < 512; i += NTHR) {
            int r = i >> 3;
            int cg = (i & 7)*8;
            int so = r*PA + cg;
            size_t ga = (size_t)(m0 + r)*HH + c*64 + cg;
            size_t gw = (size_t)(n0 + r)*HH + c*64 + cg;
            __pipeline_memcpy_async(dAh + so, g_c1h + ga, 16);
            __pipeline_memcpy_async(dAl + so, g_c1l + ga, 16);
            __pipeline_memcpy_async(dWh + so, g_Wmh + gw, 16);
            __pipeline_memcpy_async(dWl + so, g_Wml + gw, 16);
        }
    };

    pre(0, 0);
    __pipeline_commit();
    for (int c = 0; c < 16; c++) {
        if (c + 1 < 16) {
            pre(c + 1, (c + 1) & 1);
            __pipeline_commit();
            __pipeline_wait_prior(1);
        } else {
            __pipeline_wait_prior(0);
        }
        __syncthreads();
        const int s = c & 1;
        bf* cAh = base + (s*4 + 0)*MB;
        bf* cAl = base + (s*4 + 1)*MB;
        bf* cWh = base + (s*4 + 2)*MB;
        bf* cWl = base + (s*4 + 3)*MB;
        for (int ks = 0; ks < 4; ks++) {
            wmma::fragment<wmma::matrix_a, 16, 16, 16, bf, wmma::row_major> fah;
            wmma::fragment<wmma::matrix_a, 16, 16, 16, bf, wmma::row_major> fal;
            wmma::load_matrix_sync(fah, cAh + (wr*16)*PA + ks*16, PA);
            wmma::load_matrix_sync(fal, cAl + (wr*16)*PA + ks*16, PA);
            for (int j = 0; j < 2; j++) {
                wmma::fragment<wmma::matrix_b, 16, 16, 16, bf, wmma::col_major> fwh;
                wmma::fragment<wmma::matrix_b, 16, 16, 16, bf, wmma::col_major> fwl;
                const bf* ph = cWh + (wc*32 + j*16)*PA + ks*16;
                const bf* pl = cWl + (wc*32 + j*16)*PA + ks*16;
                wmma::load_matrix_sync(fwh, ph, PA);
                wmma::load_matrix_sync(fwl, pl, PA);
                wmma::mma_sync(acc[j], fah, fwh, acc[j]);
                wmma::mma_sync(acc[j], fal, fwh, acc[j]);
                wmma::mma_sync(acc[j], fah, fwl, acc[j]);
            }
        }
        __syncthreads();
    }

    for (int j = 0; j < 2; j++) {
        float* po = sout + (wr*16)*68 + wc*32 + j*16;
        wmma::store_matrix_sync(po, acc[j], 68, wmma::mem_row_major);
    }
    __syncthreads();

    for (int e = tid; e < 4096; e += NTHR) {
        int ml = e >> 6;
        int nl = e & 63;
        float v = sout[ml*68 + nl] + bm[n0 + nl];
        bf ha, hb;
        split_bf(v, ha, hb);
        size_t di = (size_t)(m0 + ml)*HH + n0 + nl;
        g_msh[di] = ha;
        g_msl[di] = hb;
    }
    __syncthreads();
}

__device__ void fin_phase(const float* __restrict__ bfin, float* outT,
                          int bid, char* smb) {
    float* cs = (float*)smb;
    float* sh = (float*)(smb + 16384);
    float* red = (float*)(smb + 18432);
    const int b0 = bid*4;
    const int tid = threadIdx.x;
    for (int idx = tid; idx < 4*HH; idx += NTHR) {
        int rr = idx >> 10;
        int kk = idx & 1023;
        cs[idx] = __ldcg(&g_c2[(size_t)(b0 + rr)*HH + kk]);
    }
    __syncthreads();
    const int v = tid & 127;
    const int rh = (tid >> 7)*2;
    float a0 = 0.f;
    float a1 = 0.f;
    for (int k = 0; k < HH; k += 4) {
        float w0 = g_WfinT[(k + 0)*128 + v];
        float w1 = g_WfinT[(k + 1)*128 + v];
        float w2 = g_WfinT[(k + 2)*128 + v];
        float w3 = g_WfinT[(k + 3)*128 + v];
        float4 c0 = *(const float4*)(cs + rh*1024 + k);
        float4 c1 = *(const float4*)(cs + rh*1024 + 1024 + k);
        a0 += c0.x*w0 + c0.y*w1 + c0.z*w2 + c0.w*w3;
        a1 += c1.x*w0 + c1.y*w1 + c1.z*w2 + c1.w*w3;
    }
    float bb = (v < VV) ? bfin[v] : 0.f;
    float v0 = (v < VV) ? (a0 + bb) : -1e30f;
    float v1 = (v < VV) ? (a1 + bb) : -1e30f;
    sh[rh*128 + v] = v0;
    sh[rh*128 + 128 + v] = v1;
    __syncthreads();
    if (tid < 4) {
        float mx = -1e30f;
        for (int j = 0; j < VV; j++) mx = fmaxf(mx, sh[tid*128 + j]);
        float s = 0.f;
        for (int j = 0; j < VV; j++) s += expf(sh[tid*128 + j] - mx);
        red[tid] = mx;
        red[4 + tid] = logf(s);
    }
    __syncthreads();
    if (v < VV) {
        float o0 = v0 - red[rh] - red[4 + rh];
        float o1 = v1 - red[rh + 1] - red[4 + rh + 1];
        outT[(size_t)(b0 + rh)*VV + v] = o0;
        outT[(size_t)(b0 + rh + 1)*VV + v] = o1;
    }
    __syncthreads();
}

__global__ void __launch_bounds__(NTHR)
lstm_tc(const float* __restrict__ bm, const float* __restrict__ bfin,
        float* __restrict__ out) {
    extern __shared__ char smb[];
    const int bid = blockIdx.x;
    unsigned expected = 0;
    const int mt = bid >> 5;
    const int nt = bid & 31;

    for (int t = 0; t < TT; t++) {
        const int cur = t & 1;
        const int nxt = cur ^ 1;
        big_phase(g_h1h[cur], g_h1l[cur], HH, 16,
                  g_xh + (long)t*BB*128, g_xl + (long)t*BB*128, 128,
                  g_W1h, g_W1l, K1P, 18,
                  g_bias1, g_c1, g_h1h[nxt], g_h1l[nxt],
                  g_c1h, g_c1l, mt, nt, smb);
        gsync(expected);
        mid_phase(bm, bid, smb);
        gsync(expected);
        big_phase(g_msh, g_msl, HH, 16,
                  g_h2h[cur], g_h2l[cur], HH,
                  g_W2h, g_W2l, K2P, 32,
                  g_bias2, g_c2, g_h2h[nxt], g_h2l[nxt],
                  (bf*)0, (bf*)0, mt, nt, smb);
        gsync(expected);
        fin_phase(bfin, out + (size_t)t*BB*VV, bid, smb);
    }
}

extern "C" void kernel_launch(void* const* d_in, const int* in_sizes,
                              int n_in, void* d_out, int out_size) {
    const float* x = (const float*)d_in[0];
    const float* Wi1 = (const float*)d_in[1];
    const float* Wh1 = (const float*)d_in[2];
    const float* bi1 = (const float*)d_in[3];
    const float* bh1 = (const float*)d_in[4];
    const float* Wm = (const float*)d_in[5];
    const float* bm = (const float*)d_in[6];
    const float* Wi2 = (const float*)d_in[7];
    const float* Wh2 = (const float*)d_in[8];
    const float* bi2 = (const float*)d_in[9];
    const float* bh2 = (const float*)d_in[10];
    const float* Wf = (const float*)d_in[11];
    const float* bfin = (const float*)d_in[12];
    float* out = (float*)d_out;

    cudaFuncSetAttribute(lstm_tc,
                         cudaFuncAttributeMaxDynamicSharedMemorySize, DSM);
    prep<<<4096, 256>>>(x, Wi1, Wh1, bi1, bh1, Wm,
                        Wi2, Wh2, bi2, bh2, Wf);
    lstm_tc<<<NB, NTHR, DSM>>>(bm, bfin, out);
}